// round 6
// baseline (speedup 1.0000x reference)
#include <cuda_runtime.h>
#include <math.h>
#include <float.h>

#define Nn 100000
#define Ff 256
#define Hh 64
#define Ee 800000
#define Rr 7
#define TILE 64
#define BS 68

typedef unsigned long long ull;

__device__ float d_h[Nn * Hh];
__device__ float d_A[Nn * Hh];
__device__ float d_B[Nn * Hh];
__device__ float d_S[Nn * Hh];
__device__ float d_cnt[Nn];
__device__ float d_C[Rr * Hh];
__device__ float d_colsum[Hh];
__device__ int   d_colmax[Hh];

__device__ __forceinline__ ull pk2(float a, float b) {
    ull r; asm("mov.b64 %0, {%1,%2};" : "=l"(r) : "f"(a), "f"(b)); return r;
}
__device__ __forceinline__ float2 upk2(ull v) {
    float2 f; asm("mov.b64 {%0,%1}, %2;" : "=f"(f.x), "=f"(f.y) : "l"(v)); return f;
}
__device__ __forceinline__ void fma2(ull &d, ull a, ull b) {
    asm("fma.rn.f32x2 %0, %1, %2, %0;" : "+l"(d) : "l"(a), "l"(b));
}
__device__ __forceinline__ void atomicMaxFloat(int* addr, float v) {
    if (v >= 0.f) atomicMax(addr, __float_as_int(v));
    else          atomicMin((unsigned int*)addr, __float_as_uint(v));
}

// colsum/colmax init folded in here
__global__ void k_relC(const float* __restrict__ rel_emb, const float* __restrict__ Wm1) {
    int t = threadIdx.x;
    if (t < Hh) { d_colsum[t] = 0.f; d_colmax[t] = __float_as_int(-FLT_MAX); }
    if (t >= Rr * Hh) return;
    int r = t / Hh, j = t % Hh;
    float s = 0.f;
    for (int k = 0; k < Hh; k++) s += rel_emb[r * Hh + k] * Wm1[(128 + k) * Hh + j];
    d_C[t] = s;
}

// row-pair GEMM core: 8 rows x 2 cols per thread, pre-duplicated weights
#define GEMM_CORE(IBUF, ACC)                                                 \
    _Pragma("unroll 4")                                                      \
    for (int k = 0; k < 64; k++) {                                           \
        ulonglong2 xa = *(const ulonglong2*)((IBUF) + k * BS + r0);          \
        ulonglong2 xb = *(const ulonglong2*)((IBUF) + k * BS + r0 + 4);      \
        ulonglong2 wd = *(const ulonglong2*)(sWd + k * 64 + c0);             \
        fma2(ACC[0][0], xa.x, wd.x); fma2(ACC[0][1], xa.x, wd.y);            \
        fma2(ACC[1][0], xa.y, wd.x); fma2(ACC[1][1], xa.y, wd.y);            \
        fma2(ACC[2][0], xb.x, wd.x); fma2(ACC[2][1], xb.x, wd.y);            \
        fma2(ACC[3][0], xb.y, wd.x); fma2(ACC[3][1], xb.y, wd.y);            \
    }

// stage a 64x64 weight block, duplicating each scalar into a packed pair
#define STAGE_WDUP(SRC)                                                      \
    _Pragma("unroll")                                                        \
    for (int i = 0; i < 4; i++) {                                            \
        int f = tid + i * 256;                                               \
        float4 w = *(const float4*)((SRC) + f * 4);                          \
        sWd[f * 4 + 0] = pk2(w.x, w.x);                                      \
        sWd[f * 4 + 1] = pk2(w.y, w.y);                                      \
        sWd[f * 4 + 2] = pk2(w.z, w.z);                                      \
        sWd[f * 4 + 3] = pk2(w.w, w.w);                                      \
    }

__global__ __launch_bounds__(256) void k_node(
    const float* __restrict__ X,
    const float* __restrict__ W1, const float* __restrict__ b1,
    const float* __restrict__ g1, const float* __restrict__ be1,
    const float* __restrict__ W2, const float* __restrict__ b2,
    const float* __restrict__ Wm1)
{
    extern __shared__ __align__(16) float sm[];
    float* buf = sm;                       // 64*BS floats
    ull*   sWd = (ull*)(sm + 64 * BS);     // 64*64 ull (32KB)
    __shared__ float sb1[64], sg1[64], sbe1[64], sb2[64];

    int tid = threadIdx.x;
    int n0 = blockIdx.x * TILE;
    int nvalid = min(TILE, Nn - n0);
    if (tid < 64) { sb1[tid] = b1[tid]; sg1[tid] = g1[tid]; sbe1[tid] = be1[tid]; sb2[tid] = b2[tid]; }

    int tx = tid & 31, ty = tid >> 5;
    int c0 = 2 * tx, r0 = 8 * ty;

    ull acc[4][2];
#pragma unroll
    for (int p = 0; p < 4; p++) { acc[p][0] = 0ull; acc[p][1] = 0ull; }

    // ---- GEMM1: Y = X @ W1  (K=256 in 4 chunks) ----
    for (int kc = 0; kc < 4; kc++) {
#pragma unroll
        for (int i = 0; i < 4; i++) {
            int f = tid + i * 256;
            int r = f & 63;
            int k4 = (f >> 6) * 4;
            float4 v = make_float4(0.f, 0.f, 0.f, 0.f);
            if (r < nvalid) v = *(const float4*)(X + (size_t)(n0 + r) * Ff + kc * 64 + k4);
            buf[(k4 + 0) * BS + r] = v.x;
            buf[(k4 + 1) * BS + r] = v.y;
            buf[(k4 + 2) * BS + r] = v.z;
            buf[(k4 + 3) * BS + r] = v.w;
        }
        STAGE_WDUP(W1 + kc * 64 * 64)
        __syncthreads();
        GEMM_CORE(buf, acc)
        __syncthreads();
    }

    // epilogue 1: y = acc + b1 -> buf (transposed); stage W2
#pragma unroll
    for (int p = 0; p < 4; p++) {
        float2 v0 = upk2(acc[p][0]);
        float2 v1 = upk2(acc[p][1]);
        float bb0 = sb1[c0], bb1 = sb1[c0 + 1];
        *(float2*)(buf + (c0    ) * BS + r0 + 2 * p) = make_float2(v0.x + bb0, v0.y + bb0);
        *(float2*)(buf + (c0 + 1) * BS + r0 + 2 * p) = make_float2(v1.x + bb1, v1.y + bb1);
    }
    STAGE_WDUP(W2)
    __syncthreads();

    // LN + relu in-place: 4 threads per row via shfl
    {
        int lr = tid >> 2, lq = tid & 3;
        int cb = lq * 16;
        float s = 0.f, s2 = 0.f;
#pragma unroll
        for (int c = 0; c < 16; c++) { float x = buf[(cb + c) * BS + lr]; s += x; s2 += x * x; }
        s  += __shfl_xor_sync(0xFFFFFFFFu, s, 1);  s2 += __shfl_xor_sync(0xFFFFFFFFu, s2, 1);
        s  += __shfl_xor_sync(0xFFFFFFFFu, s, 2);  s2 += __shfl_xor_sync(0xFFFFFFFFu, s2, 2);
        float mu = s * (1.f / 64.f);
        float var = s2 * (1.f / 64.f) - mu * mu;
        float rs = rsqrtf(var + 1e-5f);
#pragma unroll
        for (int c = 0; c < 16; c++) {
            float x = buf[(cb + c) * BS + lr];
            buf[(cb + c) * BS + lr] = fmaxf((x - mu) * rs * sg1[cb + c] + sbe1[cb + c], 0.f);
        }
    }
    __syncthreads();

    // ---- GEMM2: h = relu(h1n @ W2 + b2) ----
    ull a2[4][2];
#pragma unroll
    for (int p = 0; p < 4; p++) { a2[p][0] = 0ull; a2[p][1] = 0ull; }
    GEMM_CORE(buf, a2)
    __syncthreads();

    // epilogue 2: h -> d_h (direct, coalesced) and buf (transposed); stage Wm1a
#pragma unroll
    for (int p = 0; p < 4; p++) {
        int rr = r0 + 2 * p;
        float2 v0 = upk2(a2[p][0]);
        float2 v1 = upk2(a2[p][1]);
        float h00 = fmaxf(v0.x + sb2[c0], 0.f);     // row rr,   col c0
        float h01 = fmaxf(v1.x + sb2[c0 + 1], 0.f); // row rr,   col c0+1
        float h10 = fmaxf(v0.y + sb2[c0], 0.f);     // row rr+1, col c0
        float h11 = fmaxf(v1.y + sb2[c0 + 1], 0.f); // row rr+1, col c0+1
        if (rr     < nvalid) *(float2*)(d_h + (size_t)(n0 + rr)     * 64 + c0) = make_float2(h00, h01);
        if (rr + 1 < nvalid) *(float2*)(d_h + (size_t)(n0 + rr + 1) * 64 + c0) = make_float2(h10, h11);
        *(float2*)(buf + (c0    ) * BS + rr) = make_float2(h00, h10);
        *(float2*)(buf + (c0 + 1) * BS + rr) = make_float2(h01, h11);
    }
    STAGE_WDUP(Wm1)
    __syncthreads();

    // ---- GEMM3: A = h @ Wm1[0:64], direct coalesced stores ----
    ull a3[4][2];
#pragma unroll
    for (int p = 0; p < 4; p++) { a3[p][0] = 0ull; a3[p][1] = 0ull; }
    GEMM_CORE(buf, a3)
#pragma unroll
    for (int p = 0; p < 4; p++) {
        int rr = r0 + 2 * p;
        float2 v0 = upk2(a3[p][0]);
        float2 v1 = upk2(a3[p][1]);
        if (rr     < nvalid) *(float2*)(d_A + (size_t)(n0 + rr)     * 64 + c0) = make_float2(v0.x, v1.x);
        if (rr + 1 < nvalid) *(float2*)(d_A + (size_t)(n0 + rr + 1) * 64 + c0) = make_float2(v0.y, v1.y);
    }
    __syncthreads();
    STAGE_WDUP(Wm1 + 64 * 64)
    __syncthreads();

    // ---- GEMM4: B = h @ Wm1[64:128] ----
    ull a4[4][2];
#pragma unroll
    for (int p = 0; p < 4; p++) { a4[p][0] = 0ull; a4[p][1] = 0ull; }
    GEMM_CORE(buf, a4)
#pragma unroll
    for (int p = 0; p < 4; p++) {
        int rr = r0 + 2 * p;
        float2 v0 = upk2(a4[p][0]);
        float2 v1 = upk2(a4[p][1]);
        if (rr     < nvalid) *(float2*)(d_B + (size_t)(n0 + rr)     * 64 + c0) = make_float2(v0.x, v1.x);
        if (rr + 1 < nvalid) *(float2*)(d_B + (size_t)(n0 + rr + 1) * 64 + c0) = make_float2(v0.y, v1.y);
    }

    // ---- fused init: zero this tile's d_S rows and d_cnt ----
#pragma unroll
    for (int i = 0; i < 4; i++) {
        int f = tid + i * 256;
        int r = f >> 4, c4 = (f & 15) * 4;
        if (r < nvalid)
            *(float4*)(d_S + (size_t)(n0 + r) * 64 + c4) = make_float4(0.f, 0.f, 0.f, 0.f);
    }
    if (tid < TILE && tid < nvalid) d_cnt[n0 + tid] = 0.f;
}

__global__ __launch_bounds__(256) void k_edge(
    const float* __restrict__ edges,
    const float* __restrict__ Wm1, const float* __restrict__ bm1)
{
    __shared__ float sC[Rr * 64];
    __shared__ float swl[64], sbm1[64];
    int tid = threadIdx.x;
    for (int i = tid; i < Rr * 64; i += 256) sC[i] = d_C[i];
    if (tid < 64) { swl[tid] = Wm1[192 * 64 + tid]; sbm1[tid] = bm1[tid]; }
    __syncthreads();

    const int half = Ee / 2;
    int g = (blockIdx.x * 256 + tid) >> 4;
    int sub = tid & 15;
    if (g >= half) return;
    int c4 = sub * 4;

    float4 e0 = *(const float4*)(edges + (size_t)g * 4);
    float4 e1 = *(const float4*)(edges + (size_t)(g + half) * 4);
    int s0 = (int)e0.x, d0 = (int)e0.y, r0 = (int)e0.z; float w0 = e0.w;
    int s1 = (int)e1.x, d1 = (int)e1.y, r1 = (int)e1.z; float w1 = e1.w;

    float4 a0 = *(const float4*)(d_A + (size_t)s0 * 64 + c4);
    float4 b0 = *(const float4*)(d_B + (size_t)d0 * 64 + c4);
    float4 a1 = *(const float4*)(d_A + (size_t)s1 * 64 + c4);
    float4 b1 = *(const float4*)(d_B + (size_t)d1 * 64 + c4);

    float4 c0v = *(const float4*)(sC + r0 * 64 + c4);
    float4 c1v = *(const float4*)(sC + r1 * 64 + c4);
    float4 wl = *(const float4*)(swl + c4);
    float4 bm = *(const float4*)(sbm1 + c4);

    float4 v0, v1;
    v0.x = fmaxf(a0.x + b0.x + c0v.x + w0 * wl.x + bm.x, 0.f);
    v0.y = fmaxf(a0.y + b0.y + c0v.y + w0 * wl.y + bm.y, 0.f);
    v0.z = fmaxf(a0.z + b0.z + c0v.z + w0 * wl.z + bm.z, 0.f);
    v0.w = fmaxf(a0.w + b0.w + c0v.w + w0 * wl.w + bm.w, 0.f);
    v1.x = fmaxf(a1.x + b1.x + c1v.x + w1 * wl.x + bm.x, 0.f);
    v1.y = fmaxf(a1.y + b1.y + c1v.y + w1 * wl.y + bm.y, 0.f);
    v1.z = fmaxf(a1.z + b1.z + c1v.z + w1 * wl.z + bm.z, 0.f);
    v1.w = fmaxf(a1.w + b1.w + c1v.w + w1 * wl.w + bm.w, 0.f);

    float* p0 = d_S + (size_t)d0 * 64 + c4;
    float* p1 = d_S + (size_t)d1 * 64 + c4;
    asm volatile("red.global.add.v4.f32 [%0], {%1,%2,%3,%4};"
                 :: "l"(p0), "f"(v0.x), "f"(v0.y), "f"(v0.z), "f"(v0.w) : "memory");
    asm volatile("red.global.add.v4.f32 [%0], {%1,%2,%3,%4};"
                 :: "l"(p1), "f"(v1.x), "f"(v1.y), "f"(v1.z), "f"(v1.w) : "memory");
    if (sub == 0) { atomicAdd(&d_cnt[d0], 1.f); atomicAdd(&d_cnt[d1], 1.f); }
}

__global__ __launch_bounds__(256) void k_agg(
    const float* __restrict__ Wm2, const float* __restrict__ bm2,
    const float* __restrict__ gn,  const float* __restrict__ bn)
{
    __shared__ __align__(16) float buf[64 * BS];
    __shared__ __align__(16) float sW[64 * 64];
    __shared__ float sbm2[64], sgn[64], sbn[64];
    __shared__ float red_s[4 * 64];
    __shared__ float red_m[4 * 64];

    int tid = threadIdx.x;
    int n0 = blockIdx.x * TILE;
    int nvalid = min(TILE, Nn - n0);
    if (tid < 64) { sbm2[tid] = bm2[tid]; sgn[tid] = gn[tid]; sbn[tid] = bn[tid]; }

    for (int i = 0; i < 4; i++) {
        int f = tid + i * 256;
        int r = f & 63;
        int k4 = (f >> 6) * 4;
        float4 v = make_float4(0.f, 0.f, 0.f, 0.f);
        if (r < nvalid) v = *(const float4*)(d_S + (size_t)(n0 + r) * 64 + k4);
        buf[(k4 + 0) * BS + r] = v.x;
        buf[(k4 + 1) * BS + r] = v.y;
        buf[(k4 + 2) * BS + r] = v.z;
        buf[(k4 + 3) * BS + r] = v.w;
    }
    for (int i = 0; i < 4; i++) {
        int f = tid + i * 256;
        *(float4*)(sW + f * 4) = *(const float4*)(Wm2 + f * 4);
    }
    __syncthreads();

    int tx = tid & 31, ty = tid >> 5;
    int c0 = 2 * tx, r0 = 8 * ty;
    ull acc[4][2];
#pragma unroll
    for (int p = 0; p < 4; p++) { acc[p][0] = 0ull; acc[p][1] = 0ull; }
#pragma unroll 4
    for (int k = 0; k < 64; k++) {
        ulonglong2 xa = *(const ulonglong2*)(buf + k * BS + r0);
        ulonglong2 xb = *(const ulonglong2*)(buf + k * BS + r0 + 4);
        float2 w = *(const float2*)(sW + k * 64 + c0);
        ull wd0 = pk2(w.x, w.x), wd1 = pk2(w.y, w.y);
        fma2(acc[0][0], xa.x, wd0); fma2(acc[0][1], xa.x, wd1);
        fma2(acc[1][0], xa.y, wd0); fma2(acc[1][1], xa.y, wd1);
        fma2(acc[2][0], xb.x, wd0); fma2(acc[2][1], xb.x, wd1);
        fma2(acc[3][0], xb.y, wd0); fma2(acc[3][1], xb.y, wd1);
    }
    __syncthreads();

#pragma unroll
    for (int p = 0; p < 4; p++) {
        int rr = r0 + 2 * p;
        float cnt0 = (rr     < nvalid) ? d_cnt[n0 + rr]     : 0.f;
        float cnt1 = (rr + 1 < nvalid) ? d_cnt[n0 + rr + 1] : 0.f;
        float2 h0 = (rr     < nvalid) ? *(const float2*)(d_h + (size_t)(n0 + rr)     * 64 + c0) : make_float2(0.f, 0.f);
        float2 h1 = (rr + 1 < nvalid) ? *(const float2*)(d_h + (size_t)(n0 + rr + 1) * 64 + c0) : make_float2(0.f, 0.f);
        float2 v0 = upk2(acc[p][0]);
        float2 v1 = upk2(acc[p][1]);
        buf[(c0    ) * BS + rr    ] = v0.x + cnt0 * sbm2[c0    ] + h0.x;
        buf[(c0    ) * BS + rr + 1] = v0.y + cnt1 * sbm2[c0    ] + h1.x;
        buf[(c0 + 1) * BS + rr    ] = v1.x + cnt0 * sbm2[c0 + 1] + h0.y;
        buf[(c0 + 1) * BS + rr + 1] = v1.y + cnt1 * sbm2[c0 + 1] + h1.y;
    }
    __syncthreads();

    // LN: 4 threads per row via shfl (write normalized back to buf)
    {
        int lr = tid >> 2, lq = tid & 3;
        int cb = lq * 16;
        float s = 0.f, s2 = 0.f;
        if (lr < nvalid) {
#pragma unroll
            for (int c = 0; c < 16; c++) { float x = buf[(cb + c) * BS + lr]; s += x; s2 += x * x; }
        }
        s  += __shfl_xor_sync(0xFFFFFFFFu, s, 1);  s2 += __shfl_xor_sync(0xFFFFFFFFu, s2, 1);
        s  += __shfl_xor_sync(0xFFFFFFFFu, s, 2);  s2 += __shfl_xor_sync(0xFFFFFFFFu, s2, 2);
        if (lr < nvalid) {
            float mu = s * (1.f / 64.f);
            float var = s2 * (1.f / 64.f) - mu * mu;
            float rs = rsqrtf(var + 1e-5f);
#pragma unroll
            for (int c = 0; c < 16; c++) {
                float x = buf[(cb + c) * BS + lr];
                buf[(cb + c) * BS + lr] = (x - mu) * rs * sgn[cb + c] + sbn[cb + c];
            }
        }
    }
    __syncthreads();

    {
        int c = tid & 63, q = tid >> 6;
        float s = 0.f, m = -FLT_MAX;
        int rbeg = q * 16;
        int rend = min(rbeg + 16, nvalid);
        for (int r = rbeg; r < rend; r++) {
            float v = buf[c * BS + r];
            s += v;
            m = fmaxf(m, v);
        }
        red_s[q * 64 + c] = s;
        red_m[q * 64 + c] = m;
    }
    __syncthreads();
    if (tid < 64) {
        float s = red_s[tid] + red_s[64 + tid] + red_s[128 + tid] + red_s[192 + tid];
        float m = fmaxf(fmaxf(red_m[tid], red_m[64 + tid]),
                        fmaxf(red_m[128 + tid], red_m[192 + tid]));
        atomicAdd(&d_colsum[tid], s);
        atomicMaxFloat(&d_colmax[tid], m);
    }
}

__global__ void k_final(const float* __restrict__ Wg1, const float* __restrict__ bg1,
                        const float* __restrict__ Wg2, const float* __restrict__ bg2,
                        float* __restrict__ out)
{
    __shared__ float sg[128], st[64];
    int t = threadIdx.x;
    if (t < 64)       sg[t] = d_colsum[t] * (1.0f / (float)Nn);
    else if (t < 128) sg[t] = __int_as_float(d_colmax[t - 64]);
    __syncthreads();
    if (t < 64) {
        float s = bg1[t];
        for (int k = 0; k < 128; k++) s += sg[k] * Wg1[k * 64 + t];
        st[t] = fmaxf(s, 0.f);
    }
    __syncthreads();
    if (t < 64) {
        float s = bg2[t];
        for (int k = 0; k < 64; k++) s += st[k] * Wg2[k * 64 + t];
        out[t] = s;
    }
}

extern "C" void kernel_launch(void* const* d_in, const int* in_sizes, int n_in,
                              void* d_out, int out_size)
{
    const float* X      = (const float*)d_in[0];
    const float* edges  = (const float*)d_in[1];
    const float* W1     = (const float*)d_in[2];
    const float* b1     = (const float*)d_in[3];
    const float* g1     = (const float*)d_in[4];
    const float* be1    = (const float*)d_in[5];
    const float* W2     = (const float*)d_in[6];
    const float* b2     = (const float*)d_in[7];
    const float* rel_emb= (const float*)d_in[8];
    const float* Wm1    = (const float*)d_in[9];
    const float* bm1    = (const float*)d_in[10];
    const float* Wm2    = (const float*)d_in[11];
    const float* bm2    = (const float*)d_in[12];
    const float* gn     = (const float*)d_in[13];
    const float* bn     = (const float*)d_in[14];
    const float* Wg1    = (const float*)d_in[15];
    const float* bg1    = (const float*)d_in[16];
    const float* Wg2    = (const float*)d_in[17];
    const float* bg2    = (const float*)d_in[18];
    float* out = (float*)d_out;

    int node_smem = 64 * BS * 4 + 64 * 64 * 8;   // buf + duplicated weights = 50176 B
    cudaFuncSetAttribute(k_node, cudaFuncAttributeMaxDynamicSharedMemorySize, node_smem);

    k_relC<<<1, 512>>>(rel_emb, Wm1);
    int nblocks = (Nn + TILE - 1) / TILE;
    k_node<<<nblocks, 256, node_smem>>>(X, W1, b1, g1, be1, W2, b2, Wm1);
    int eblocks = ((Ee / 2) * 16 + 255) / 256;
    k_edge<<<eblocks, 256>>>(edges, Wm1, bm1);
    k_agg<<<nblocks, 256>>>(Wm2, bm2, gn, bn);
    k_final<<<1, 128>>>(Wg1, bg1, Wg2, bg2, out);
}

// round 7
// speedup vs baseline: 1.1780x; 1.1780x over previous
#include <cuda_runtime.h>
#include <math.h>
#include <float.h>

#define Nn 100000
#define Ff 256
#define Hh 64
#define Ee 800000
#define Rr 7
#define TILE 64
#define BS 68

typedef unsigned long long ull;

__device__ float d_h[Nn * Hh];
__device__ float d_A[Nn * Hh];
__device__ float d_B[Nn * Hh];
__device__ float d_S[Nn * Hh];
__device__ float d_cnt[Nn];
__device__ float d_C[Rr * Hh];
__device__ float d_colsum[Hh];
__device__ int   d_colmax[Hh];

__device__ __forceinline__ ull pk2(float a, float b) {
    ull r; asm("mov.b64 %0, {%1,%2};" : "=l"(r) : "f"(a), "f"(b)); return r;
}
__device__ __forceinline__ float2 upk2(ull v) {
    float2 f; asm("mov.b64 {%0,%1}, %2;" : "=f"(f.x), "=f"(f.y) : "l"(v)); return f;
}
__device__ __forceinline__ void fma2(ull &d, ull a, ull b) {
    asm("fma.rn.f32x2 %0, %1, %2, %0;" : "+l"(d) : "l"(a), "l"(b));
}
__device__ __forceinline__ void atomicMaxFloat(int* addr, float v) {
    if (v >= 0.f) atomicMax(addr, __float_as_int(v));
    else          atomicMin((unsigned int*)addr, __float_as_uint(v));
}

// colsum/colmax init folded in here (k_init removed)
__global__ void k_relC(const float* __restrict__ rel_emb, const float* __restrict__ Wm1) {
    int t = threadIdx.x;
    if (t < Hh) { d_colsum[t] = 0.f; d_colmax[t] = __float_as_int(-FLT_MAX); }
    if (t >= Rr * Hh) return;
    int r = t / Hh, j = t % Hh;
    float s = 0.f;
    for (int k = 0; k < Hh; k++) s += rel_emb[r * Hh + k] * Wm1[(128 + k) * Hh + j];
    d_C[t] = s;
}

__global__ __launch_bounds__(256) void k_node(
    const float* __restrict__ X,
    const float* __restrict__ W1, const float* __restrict__ b1,
    const float* __restrict__ g1, const float* __restrict__ be1,
    const float* __restrict__ W2, const float* __restrict__ b2,
    const float* __restrict__ Wm1)
{
    __shared__ __align__(16) float buf[64 * BS];
    __shared__ __align__(16) float sW[64 * 64];
    __shared__ float sb1[64], sg1[64], sbe1[64], sb2[64];

    int tid = threadIdx.x;
    int n0 = blockIdx.x * TILE;
    int nvalid = min(TILE, Nn - n0);
    if (tid < 64) { sb1[tid] = b1[tid]; sg1[tid] = g1[tid]; sbe1[tid] = be1[tid]; sb2[tid] = b2[tid]; }

    int tx = tid & 31, ty = tid >> 5;
    int c0 = 2 * tx, r0 = 8 * ty;

    ull acc[4][2];
#pragma unroll
    for (int p = 0; p < 4; p++) { acc[p][0] = 0ull; acc[p][1] = 0ull; }

    // GEMM1: Y = X @ W1  (K=256 in 4 chunks of 64)
    for (int kc = 0; kc < 4; kc++) {
        for (int i = 0; i < 4; i++) {
            int f = tid + i * 256;
            int r = f & 63;
            int k4 = (f >> 6) * 4;
            float4 v = make_float4(0.f, 0.f, 0.f, 0.f);
            if (r < nvalid) v = *(const float4*)(X + (size_t)(n0 + r) * Ff + kc * 64 + k4);
            buf[(k4 + 0) * BS + r] = v.x;
            buf[(k4 + 1) * BS + r] = v.y;
            buf[(k4 + 2) * BS + r] = v.z;
            buf[(k4 + 3) * BS + r] = v.w;
        }
        for (int i = 0; i < 4; i++) {
            int f = tid + i * 256;
            *(float4*)(sW + f * 4) = *(const float4*)(W1 + kc * 64 * 64 + f * 4);
        }
        __syncthreads();
#pragma unroll 4
        for (int k = 0; k < 64; k++) {
            ulonglong2 xa = *(const ulonglong2*)(buf + k * BS + r0);
            ulonglong2 xb = *(const ulonglong2*)(buf + k * BS + r0 + 4);
            float2 w = *(const float2*)(sW + k * 64 + c0);
            ull wd0 = pk2(w.x, w.x), wd1 = pk2(w.y, w.y);
            fma2(acc[0][0], xa.x, wd0); fma2(acc[0][1], xa.x, wd1);
            fma2(acc[1][0], xa.y, wd0); fma2(acc[1][1], xa.y, wd1);
            fma2(acc[2][0], xb.x, wd0); fma2(acc[2][1], xb.x, wd1);
            fma2(acc[3][0], xb.y, wd0); fma2(acc[3][1], xb.y, wd1);
        }
        __syncthreads();
    }

#pragma unroll
    for (int p = 0; p < 4; p++)
#pragma unroll
        for (int c = 0; c < 2; c++) {
            float2 v = upk2(acc[p][c]);
            float bb = sb1[c0 + c];
            *(float2*)(buf + (c0 + c) * BS + r0 + 2 * p) = make_float2(v.x + bb, v.y + bb);
        }
    for (int i = 0; i < 4; i++) {
        int f = tid + i * 256;
        *(float4*)(sW + f * 4) = *(const float4*)(W2 + f * 4);
    }
    __syncthreads();

    if (tid < 64) {
        int r = tid;
        float s = 0.f, s2 = 0.f;
        for (int c = 0; c < 64; c++) { float x = buf[c * BS + r]; s += x; s2 += x * x; }
        float mu = s * (1.f / 64.f);
        float var = s2 * (1.f / 64.f) - mu * mu;
        float rs = rsqrtf(var + 1e-5f);
        for (int c = 0; c < 64; c++) {
            float x = buf[c * BS + r];
            float v = (x - mu) * rs * sg1[c] + sbe1[c];
            buf[c * BS + r] = fmaxf(v, 0.f);
        }
    }
    __syncthreads();

    // GEMM2: h = relu(h1n @ W2 + b2)
    ull a2[4][2];
#pragma unroll
    for (int p = 0; p < 4; p++) { a2[p][0] = 0ull; a2[p][1] = 0ull; }
#pragma unroll 4
    for (int k = 0; k < 64; k++) {
        ulonglong2 xa = *(const ulonglong2*)(buf + k * BS + r0);
        ulonglong2 xb = *(const ulonglong2*)(buf + k * BS + r0 + 4);
        float2 w = *(const float2*)(sW + k * 64 + c0);
        ull wd0 = pk2(w.x, w.x), wd1 = pk2(w.y, w.y);
        fma2(a2[0][0], xa.x, wd0); fma2(a2[0][1], xa.x, wd1);
        fma2(a2[1][0], xa.y, wd0); fma2(a2[1][1], xa.y, wd1);
        fma2(a2[2][0], xb.x, wd0); fma2(a2[2][1], xb.x, wd1);
        fma2(a2[3][0], xb.y, wd0); fma2(a2[3][1], xb.y, wd1);
    }
    __syncthreads();

#pragma unroll
    for (int p = 0; p < 4; p++)
#pragma unroll
        for (int c = 0; c < 2; c++) {
            float2 v = upk2(a2[p][c]);
            float bb = sb2[c0 + c];
            *(float2*)(buf + (c0 + c) * BS + r0 + 2 * p) =
                make_float2(fmaxf(v.x + bb, 0.f), fmaxf(v.y + bb, 0.f));
        }
    for (int i = 0; i < 4; i++) {
        int f = tid + i * 256;
        *(float4*)(sW + f * 4) = *(const float4*)(Wm1 + f * 4);
    }
    __syncthreads();

    // store h (coalesced)
    for (int i = 0; i < 4; i++) {
        int f = tid + i * 256;
        int r = f >> 4, c4 = (f & 15) * 4;
        if (r < nvalid) {
            float4 v;
            v.x = buf[(c4 + 0) * BS + r]; v.y = buf[(c4 + 1) * BS + r];
            v.z = buf[(c4 + 2) * BS + r]; v.w = buf[(c4 + 3) * BS + r];
            *(float4*)(d_h + (size_t)(n0 + r) * 64 + c4) = v;
        }
    }

    // GEMM3: A = h @ Wm1[0:64]  (col-pair layout)
    int tx2 = tid & 15, ty2 = tid >> 4;
    int cc0 = 4 * tx2, rr0 = 4 * ty2;
    ull a3[4][2];
#pragma unroll
    for (int p = 0; p < 4; p++) { a3[p][0] = 0ull; a3[p][1] = 0ull; }
#pragma unroll 4
    for (int k = 0; k < 64; k++) {
        float x0 = buf[k * BS + rr0 + 0];
        float x1 = buf[k * BS + rr0 + 1];
        float x2 = buf[k * BS + rr0 + 2];
        float x3 = buf[k * BS + rr0 + 3];
        ulonglong2 wp = *(const ulonglong2*)(sW + k * 64 + cc0);
        ull xd0 = pk2(x0, x0), xd1 = pk2(x1, x1), xd2 = pk2(x2, x2), xd3 = pk2(x3, x3);
        fma2(a3[0][0], xd0, wp.x); fma2(a3[0][1], xd0, wp.y);
        fma2(a3[1][0], xd1, wp.x); fma2(a3[1][1], xd1, wp.y);
        fma2(a3[2][0], xd2, wp.x); fma2(a3[2][1], xd2, wp.y);
        fma2(a3[3][0], xd3, wp.x); fma2(a3[3][1], xd3, wp.y);
    }
    __syncthreads();
    for (int i = 0; i < 4; i++) {
        int f = tid + i * 256;
        *(float4*)(sW + f * 4) = *(const float4*)(Wm1 + 64 * 64 + f * 4);
    }
#pragma unroll
    for (int p = 0; p < 4; p++) {
        int rr = rr0 + p;
        if (rr < nvalid) {
#pragma unroll
            for (int q = 0; q < 2; q++) {
                float2 v = upk2(a3[p][q]);
                *(float2*)(d_A + (size_t)(n0 + rr) * 64 + cc0 + 2 * q) = v;
            }
        }
    }
    __syncthreads();

    // GEMM4: B = h @ Wm1[64:128]
    ull a4[4][2];
#pragma unroll
    for (int p = 0; p < 4; p++) { a4[p][0] = 0ull; a4[p][1] = 0ull; }
#pragma unroll 4
    for (int k = 0; k < 64; k++) {
        float x0 = buf[k * BS + rr0 + 0];
        float x1 = buf[k * BS + rr0 + 1];
        float x2 = buf[k * BS + rr0 + 2];
        float x3 = buf[k * BS + rr0 + 3];
        ulonglong2 wp = *(const ulonglong2*)(sW + k * 64 + cc0);
        ull xd0 = pk2(x0, x0), xd1 = pk2(x1, x1), xd2 = pk2(x2, x2), xd3 = pk2(x3, x3);
        fma2(a4[0][0], xd0, wp.x); fma2(a4[0][1], xd0, wp.y);
        fma2(a4[1][0], xd1, wp.x); fma2(a4[1][1], xd1, wp.y);
        fma2(a4[2][0], xd2, wp.x); fma2(a4[2][1], xd2, wp.y);
        fma2(a4[3][0], xd3, wp.x); fma2(a4[3][1], xd3, wp.y);
    }
#pragma unroll
    for (int p = 0; p < 4; p++) {
        int rr = rr0 + p;
        if (rr < nvalid) {
#pragma unroll
            for (int q = 0; q < 2; q++) {
                float2 v = upk2(a4[p][q]);
                *(float2*)(d_B + (size_t)(n0 + rr) * 64 + cc0 + 2 * q) = v;
            }
        }
    }

    // fused init: zero this tile's d_S rows and d_cnt (replaces k_init)
#pragma unroll
    for (int i = 0; i < 4; i++) {
        int f = tid + i * 256;
        int r = f >> 4, c4 = (f & 15) * 4;
        if (r < nvalid)
            *(float4*)(d_S + (size_t)(n0 + r) * 64 + c4) = make_float4(0.f, 0.f, 0.f, 0.f);
    }
    if (tid < TILE && tid < nvalid) d_cnt[n0 + tid] = 0.f;
}

// Edge pass: 2 edges per 16-lane group
__global__ __launch_bounds__(256) void k_edge(
    const float* __restrict__ edges,
    const float* __restrict__ Wm1, const float* __restrict__ bm1)
{
    __shared__ float sC[Rr * 64];
    __shared__ float swl[64], sbm1[64];
    int tid = threadIdx.x;
    for (int i = tid; i < Rr * 64; i += 256) sC[i] = d_C[i];
    if (tid < 64) { swl[tid] = Wm1[192 * 64 + tid]; sbm1[tid] = bm1[tid]; }
    __syncthreads();

    const int half = Ee / 2;
    int g = (blockIdx.x * 256 + tid) >> 4;
    int sub = tid & 15;
    if (g >= half) return;
    int c4 = sub * 4;

    float4 e0 = *(const float4*)(edges + (size_t)g * 4);
    float4 e1 = *(const float4*)(edges + (size_t)(g + half) * 4);
    int s0 = (int)e0.x, d0 = (int)e0.y, r0 = (int)e0.z; float w0 = e0.w;
    int s1 = (int)e1.x, d1 = (int)e1.y, r1 = (int)e1.z; float w1 = e1.w;

    float4 a0 = *(const float4*)(d_A + (size_t)s0 * 64 + c4);
    float4 b0 = *(const float4*)(d_B + (size_t)d0 * 64 + c4);
    float4 a1 = *(const float4*)(d_A + (size_t)s1 * 64 + c4);
    float4 b1 = *(const float4*)(d_B + (size_t)d1 * 64 + c4);

    float4 c0v = *(const float4*)(sC + r0 * 64 + c4);
    float4 c1v = *(const float4*)(sC + r1 * 64 + c4);
    float4 wl = *(const float4*)(swl + c4);
    float4 bm = *(const float4*)(sbm1 + c4);

    float4 v0, v1;
    v0.x = fmaxf(a0.x + b0.x + c0v.x + w0 * wl.x + bm.x, 0.f);
    v0.y = fmaxf(a0.y + b0.y + c0v.y + w0 * wl.y + bm.y, 0.f);
    v0.z = fmaxf(a0.z + b0.z + c0v.z + w0 * wl.z + bm.z, 0.f);
    v0.w = fmaxf(a0.w + b0.w + c0v.w + w0 * wl.w + bm.w, 0.f);
    v1.x = fmaxf(a1.x + b1.x + c1v.x + w1 * wl.x + bm.x, 0.f);
    v1.y = fmaxf(a1.y + b1.y + c1v.y + w1 * wl.y + bm.y, 0.f);
    v1.z = fmaxf(a1.z + b1.z + c1v.z + w1 * wl.z + bm.z, 0.f);
    v1.w = fmaxf(a1.w + b1.w + c1v.w + w1 * wl.w + bm.w, 0.f);

    float* p0 = d_S + (size_t)d0 * 64 + c4;
    float* p1 = d_S + (size_t)d1 * 64 + c4;
    asm volatile("red.global.add.v4.f32 [%0], {%1,%2,%3,%4};"
                 :: "l"(p0), "f"(v0.x), "f"(v0.y), "f"(v0.z), "f"(v0.w) : "memory");
    asm volatile("red.global.add.v4.f32 [%0], {%1,%2,%3,%4};"
                 :: "l"(p1), "f"(v1.x), "f"(v1.y), "f"(v1.z), "f"(v1.w) : "memory");
    if (sub == 0) { atomicAdd(&d_cnt[d0], 1.f); atomicAdd(&d_cnt[d1], 1.f); }
}

__global__ __launch_bounds__(256) void k_agg(
    const float* __restrict__ Wm2, const float* __restrict__ bm2,
    const float* __restrict__ gn,  const float* __restrict__ bn)
{
    __shared__ __align__(16) float buf[64 * BS];
    __shared__ __align__(16) float sW[64 * 64];
    __shared__ float sbm2[64], sgn[64], sbn[64];
    __shared__ float red_s[4 * 64];
    __shared__ float red_m[4 * 64];

    int tid = threadIdx.x;
    int n0 = blockIdx.x * TILE;
    int nvalid = min(TILE, Nn - n0);
    if (tid < 64) { sbm2[tid] = bm2[tid]; sgn[tid] = gn[tid]; sbn[tid] = bn[tid]; }

    for (int i = 0; i < 4; i++) {
        int f = tid + i * 256;
        int r = f & 63;
        int k4 = (f >> 6) * 4;
        float4 v = make_float4(0.f, 0.f, 0.f, 0.f);
        if (r < nvalid) v = *(const float4*)(d_S + (size_t)(n0 + r) * 64 + k4);
        buf[(k4 + 0) * BS + r] = v.x;
        buf[(k4 + 1) * BS + r] = v.y;
        buf[(k4 + 2) * BS + r] = v.z;
        buf[(k4 + 3) * BS + r] = v.w;
    }
    for (int i = 0; i < 4; i++) {
        int f = tid + i * 256;
        *(float4*)(sW + f * 4) = *(const float4*)(Wm2 + f * 4);
    }
    __syncthreads();

    int tx = tid & 31, ty = tid >> 5;
    int c0 = 2 * tx, r0 = 8 * ty;
    ull acc[4][2];
#pragma unroll
    for (int p = 0; p < 4; p++) { acc[p][0] = 0ull; acc[p][1] = 0ull; }
#pragma unroll 4
    for (int k = 0; k < 64; k++) {
        ulonglong2 xa = *(const ulonglong2*)(buf + k * BS + r0);
        ulonglong2 xb = *(const ulonglong2*)(buf + k * BS + r0 + 4);
        float2 w = *(const float2*)(sW + k * 64 + c0);
        ull wd0 = pk2(w.x, w.x), wd1 = pk2(w.y, w.y);
        fma2(acc[0][0], xa.x, wd0); fma2(acc[0][1], xa.x, wd1);
        fma2(acc[1][0], xa.y, wd0); fma2(acc[1][1], xa.y, wd1);
        fma2(acc[2][0], xb.x, wd0); fma2(acc[2][1], xb.x, wd1);
        fma2(acc[3][0], xb.y, wd0); fma2(acc[3][1], xb.y, wd1);
    }
    __syncthreads();

#pragma unroll
    for (int p = 0; p < 4; p++) {
        int rr = r0 + 2 * p;
        float cnt0 = (rr     < nvalid) ? d_cnt[n0 + rr]     : 0.f;
        float cnt1 = (rr + 1 < nvalid) ? d_cnt[n0 + rr + 1] : 0.f;
        float2 h0 = (rr     < nvalid) ? *(const float2*)(d_h + (size_t)(n0 + rr)     * 64 + c0) : make_float2(0.f, 0.f);
        float2 h1 = (rr + 1 < nvalid) ? *(const float2*)(d_h + (size_t)(n0 + rr + 1) * 64 + c0) : make_float2(0.f, 0.f);
        float2 v0 = upk2(acc[p][0]);
        float2 v1 = upk2(acc[p][1]);
        buf[(c0    ) * BS + rr    ] = v0.x + cnt0 * sbm2[c0    ] + h0.x;
        buf[(c0    ) * BS + rr + 1] = v0.y + cnt1 * sbm2[c0    ] + h1.x;
        buf[(c0 + 1) * BS + rr    ] = v1.x + cnt0 * sbm2[c0 + 1] + h0.y;
        buf[(c0 + 1) * BS + rr + 1] = v1.y + cnt1 * sbm2[c0 + 1] + h1.y;
    }
    __syncthreads();

    if (tid < 64 && tid < nvalid) {
        int r = tid;
        float s = 0.f, s2 = 0.f;
        for (int c = 0; c < 64; c++) { float x = buf[c * BS + r]; s += x; s2 += x * x; }
        float mu = s * (1.f / 64.f);
        float var = s2 * (1.f / 64.f) - mu * mu;
        float rs = rsqrtf(var + 1e-5f);
        for (int c = 0; c < 64; c++) {
            float x = buf[c * BS + r];
            buf[c * BS + r] = (x - mu) * rs * sgn[c] + sbn[c];
        }
    }
    __syncthreads();

    {
        int c = tid & 63, q = tid >> 6;
        float s = 0.f, m = -FLT_MAX;
        int rbeg = q * 16;
        int rend = min(rbeg + 16, nvalid);
        for (int r = rbeg; r < rend; r++) {
            float v = buf[c * BS + r];
            s += v;
            m = fmaxf(m, v);
        }
        red_s[q * 64 + c] = s;
        red_m[q * 64 + c] = m;
    }
    __syncthreads();
    if (tid < 64) {
        float s = red_s[tid] + red_s[64 + tid] + red_s[128 + tid] + red_s[192 + tid];
        float m = fmaxf(fmaxf(red_m[tid], red_m[64 + tid]),
                        fmaxf(red_m[128 + tid], red_m[192 + tid]));
        atomicAdd(&d_colsum[tid], s);
        atomicMaxFloat(&d_colmax[tid], m);
    }
}

__global__ void k_final(const float* __restrict__ Wg1, const float* __restrict__ bg1,
                        const float* __restrict__ Wg2, const float* __restrict__ bg2,
                        float* __restrict__ out)
{
    __shared__ float sg[128], st[64];
    int t = threadIdx.x;
    if (t < 64)       sg[t] = d_colsum[t] * (1.0f / (float)Nn);
    else if (t < 128) sg[t] = __int_as_float(d_colmax[t - 64]);
    __syncthreads();
    if (t < 64) {
        float s = bg1[t];
        for (int k = 0; k < 128; k++) s += sg[k] * Wg1[k * 64 + t];
        st[t] = fmaxf(s, 0.f);
    }
    __syncthreads();
    if (t < 64) {
        float s = bg2[t];
        for (int k = 0; k < 64; k++) s += st[k] * Wg2[k * 64 + t];
        out[t] = s;
    }
}

extern "C" void kernel_launch(void* const* d_in, const int* in_sizes, int n_in,
                              void* d_out, int out_size)
{
    const float* X      = (const float*)d_in[0];
    const float* edges  = (const float*)d_in[1];
    const float* W1     = (const float*)d_in[2];
    const float* b1     = (const float*)d_in[3];
    const float* g1     = (const float*)d_in[4];
    const float* be1    = (const float*)d_in[5];
    const float* W2     = (const float*)d_in[6];
    const float* b2     = (const float*)d_in[7];
    const float* rel_emb= (const float*)d_in[8];
    const float* Wm1    = (const float*)d_in[9];
    const float* bm1    = (const float*)d_in[10];
    const float* Wm2    = (const float*)d_in[11];
    const float* bm2    = (const float*)d_in[12];
    const float* gn     = (const float*)d_in[13];
    const float* bn     = (const float*)d_in[14];
    const float* Wg1    = (const float*)d_in[15];
    const float* bg1    = (const float*)d_in[16];
    const float* Wg2    = (const float*)d_in[17];
    const float* bg2    = (const float*)d_in[18];
    float* out = (float*)d_out;

    k_relC<<<1, 512>>>(rel_emb, Wm1);
    int nblocks = (Nn + TILE - 1) / TILE;
    k_node<<<nblocks, 256>>>(X, W1, b1, g1, be1, W2, b2, Wm1);
    int eblocks = ((Ee / 2) * 16 + 255) / 256;
    k_edge<<<eblocks, 256>>>(edges, Wm1, bm1);
    k_agg<<<nblocks, 256>>>(Wm2, bm2, gn, bn);
    k_final<<<1, 128>>>(Wg1, bg1, Wg2, bg2, out);
}